// round 17
// baseline (speedup 1.0000x reference)
#include <cuda_runtime.h>
#include <cstdint>

#define H 128
#define B 1024
#define K 10
#define NSAMP (B + B * K)   // 11264
#define REL 1000
#define MARGIN 1.0f
#define STHREADS 256        // 8 warps; 2 samples per warp per pass -> 16/pass
#define GRID_CTAS 148
#define RSZ (H * H)         // 16384 floats per relation

// ---------------- global scratch (zero-initialized at load) ----------------
__device__ int          g_hist[REL];        // re-zeroed by scan_kernel each run
__device__ int          g_bin_start[REL + 1];
__device__ int          g_cursor[REL];
__device__ int          g_sorted_sid[NSAMP];
__device__ int          g_sorted_h[NSAMP];
__device__ int          g_sorted_t[NSAMP];
__device__ float        g_scores[NSAMP];    // written once per sample (atomicExch)
__device__ unsigned int g_done;             // last CTA resets -> replay-safe

// ---------------- kernel 1: histogram (44 x 256) ----------------
__global__ void __launch_bounds__(256) hist_kernel(
    const int* __restrict__ pos_r, const int* __restrict__ neg_r)
{
    const int s = blockIdx.x * 256 + threadIdx.x;   // exactly NSAMP threads
    const int r = (s < B) ? pos_r[s] : neg_r[s - B];
    atomicAdd(&g_hist[r], 1);
}

// ---------------- kernel 2: exclusive scan over 1000 bins (1 block) ----------------
__global__ void __launch_bounds__(1024) scan_kernel()
{
    __shared__ int wsum[32];
    const int t    = threadIdx.x;
    const int lane = t & 31;
    const int wid  = t >> 5;

    const int cnt = (t < REL) ? g_hist[t] : 0;
    int v = cnt;
#pragma unroll
    for (int off = 1; off < 32; off <<= 1) {
        int u = __shfl_up_sync(0xffffffffu, v, off);
        if (lane >= off) v += u;
    }
    if (lane == 31) wsum[wid] = v;
    __syncthreads();
    if (wid == 0) {
        int x = wsum[lane];
#pragma unroll
        for (int off = 1; off < 32; off <<= 1) {
            int u = __shfl_up_sync(0xffffffffu, x, off);
            if (lane >= off) x += u;
        }
        wsum[lane] = x;
    }
    __syncthreads();

    const int excl = v - cnt + ((wid > 0) ? wsum[wid - 1] : 0);
    if (t < REL) {
        g_bin_start[t] = excl;
        g_cursor[t]    = excl;
        g_hist[t]      = 0;          // ready for next graph replay
    }
    if (t == REL - 1) g_bin_start[REL] = excl + cnt;
}

// ---------------- kernel 3: scatter into bins (44 x 256) ----------------
__global__ void __launch_bounds__(256) scatter_kernel(
    const int* __restrict__ pos_h, const int* __restrict__ pos_t, const int* __restrict__ pos_r,
    const int* __restrict__ neg_h, const int* __restrict__ neg_t, const int* __restrict__ neg_r)
{
    const int s = blockIdx.x * 256 + threadIdx.x;
    int r, hi, ti;
    if (s < B) { r = pos_r[s]; hi = pos_h[s]; ti = pos_t[s]; }
    else       { int n = s - B; r = neg_r[n]; hi = neg_h[n]; ti = neg_t[n]; }
    int pos = atomicAdd(&g_cursor[r], 1);
    g_sorted_sid[pos] = s;
    g_sorted_h[pos]   = hi;
    g_sorted_t[pos]   = ti;
}

// ---------------- kernel 4: persistent CTAs, full-R double buffer ----------------
// 148 persistent CTAs; each owns relations r = bid, bid+148, ...  Full 64KB R in
// smem buffer p while the next relation's R streams into p^1 via cp.async.
// Warps process 2 samples each with h in registers (shfl broadcast) -> no
// staging smem, no per-chunk barriers.
__global__ void __launch_bounds__(STHREADS, 1) score_loss_kernel(
    const float* __restrict__ ent,
    const float* __restrict__ rel,
    float* __restrict__ out)
{
    extern __shared__ float sm[];           // 2 x 16384 floats (128 KB)
    __shared__ int s_last;
    __shared__ float ws[STHREADS / 32];

    const int tid  = threadIdx.x;
    const int lane = tid & 31;
    const int w    = tid >> 5;

    auto prefetch = [&](int buf, int r) {
        const char* Rg = (const char*)(rel + (size_t)r * RSZ);
        uint32_t sR = (uint32_t)__cvta_generic_to_shared(sm + buf * RSZ);
#pragma unroll
        for (int k = 0; k < (RSZ * 4) / (16 * STHREADS); ++k) {   // 16 iters
            int off = (k * STHREADS + tid) * 16;
            asm volatile("cp.async.cg.shared.global [%0], [%1], 16;"
                         :: "r"(sR + off), "l"(Rg + off));
        }
        asm volatile("cp.async.commit_group;");
    };

    int r = blockIdx.x;
    int p = 0;
    if (r < REL) prefetch(0, r);

    while (r < REL) {
        const int rn = r + GRID_CTAS;
        if (rn < REL) {
            prefetch(p ^ 1, rn);
            asm volatile("cp.async.wait_group 1;");
        } else {
            asm volatile("cp.async.wait_group 0;");
        }
        __syncthreads();                     // Rsh[p] complete, visible

        const int beg = g_bin_start[r];
        const int m   = g_bin_start[r + 1] - beg;
        const float4* __restrict__ R4 = (const float4*)(sm + p * RSZ);

        for (int s0 = w * 2; s0 < m; s0 += 16) {
            const int s1 = s0 + 1;
            const bool v1 = (s1 < m);
            // uniform warp loads of indices (L2/L1 hot)
            const int h0i = g_sorted_h[beg + s0];
            const int h1i = v1 ? g_sorted_h[beg + s1] : h0i;
            const int t0i = g_sorted_t[beg + s0];
            const int t1i = v1 ? g_sorted_t[beg + s1] : t0i;
            const int d0  = g_sorted_sid[beg + s0];
            const int d1  = v1 ? g_sorted_sid[beg + s1] : -1;

            // h into registers: 4 coalesced 128B loads per sample
            float h0[4], h1[4];
#pragma unroll
            for (int ii = 0; ii < 4; ++ii) {
                h0[ii] = ent[(size_t)h0i * H + ii * 32 + lane];
                h1[ii] = ent[(size_t)h1i * H + ii * 32 + lane];
            }
            // t rows batched up front
            float4 tv0 = __ldg((const float4*)(ent + (size_t)t0i * H) + lane);
            float4 tv1 = __ldg((const float4*)(ent + (size_t)t1i * H) + lane);

            float4 a0 = make_float4(0.f, 0.f, 0.f, 0.f);
            float4 a1 = a0;

#pragma unroll
            for (int ii = 0; ii < 4; ++ii) {
#pragma unroll
                for (int i2 = 0; i2 < 32; ++i2) {
                    const float4 rv = R4[(ii * 32 + i2) * 32 + lane];
                    const float b0 = __shfl_sync(0xffffffffu, h0[ii], i2);
                    const float b1 = __shfl_sync(0xffffffffu, h1[ii], i2);
                    a0.x = fmaf(rv.x, b0, a0.x); a0.y = fmaf(rv.y, b0, a0.y);
                    a0.z = fmaf(rv.z, b0, a0.z); a0.w = fmaf(rv.w, b0, a0.w);
                    a1.x = fmaf(rv.x, b1, a1.x); a1.y = fmaf(rv.y, b1, a1.y);
                    a1.z = fmaf(rv.z, b1, a1.z); a1.w = fmaf(rv.w, b1, a1.w);
                }
            }

            float v = a0.x * tv0.x + a0.y * tv0.y + a0.z * tv0.z + a0.w * tv0.w;
            float u = a1.x * tv1.x + a1.y * tv1.y + a1.z * tv1.z + a1.w * tv1.w;
#pragma unroll
            for (int off = 16; off > 0; off >>= 1) {
                v += __shfl_down_sync(0xffffffffu, v, off);
                u += __shfl_down_sync(0xffffffffu, u, off);
            }
            if (lane == 0) {
                atomicExch(&g_scores[d0], v);           // full score, coherent store
                if (d1 >= 0) atomicExch(&g_scores[d1], u);
            }
        }

        __syncthreads();                     // all warps done with Rsh[p]
        p ^= 1;
        r = rn;
    }

    // ---- completion counting; last CTA computes the loss ----
    if (tid == 0) {
        __threadfence();
        unsigned int old = atomicAdd(&g_done, 1u);
        s_last = (old == (unsigned int)(gridDim.x - 1)) ? 1 : 0;
    }
    __syncthreads();

    if (s_last) {
        if (tid == 0) { g_done = 0; __threadfence(); }

        float l = 0.0f;
#pragma unroll
        for (int q = 0; q < B / STHREADS; ++q) {
            const int b = q * STHREADS + tid;
            const float ps = g_scores[b];
            float n = 0.0f;
#pragma unroll
            for (int k = 0; k < K; ++k)
                n += g_scores[B + b * K + k];
            n *= (1.0f / (float)K);
            l += fmaxf(n - ps + MARGIN, 0.0f);
        }

#pragma unroll
        for (int off = 16; off > 0; off >>= 1)
            l += __shfl_down_sync(0xffffffffu, l, off);

        if (lane == 0) ws[w] = l;
        __syncthreads();
        if (tid < 32) {
            float v = (tid < STHREADS / 32) ? ws[tid] : 0.0f;
#pragma unroll
            for (int off = 4; off > 0; off >>= 1)
                v += __shfl_down_sync(0xffffffffu, v, off);
            if (tid == 0) out[0] = v;
        }
    }
}

// ---------------- launcher ----------------
extern "C" void kernel_launch(void* const* d_in, const int* in_sizes, int n_in,
                              void* d_out, int out_size)
{
    const float* ent   = (const float*)d_in[0];
    const float* rel   = (const float*)d_in[1];
    const int*   pos_h = (const int*)d_in[2];
    const int*   pos_t = (const int*)d_in[3];
    const int*   pos_r = (const int*)d_in[4];
    const int*   neg_h = (const int*)d_in[5];
    const int*   neg_t = (const int*)d_in[6];
    const int*   neg_r = (const int*)d_in[7];
    float* out = (float*)d_out;

    const int smem = 2 * RSZ * (int)sizeof(float);   // 128 KB
    cudaFuncSetAttribute(score_loss_kernel,
                         cudaFuncAttributeMaxDynamicSharedMemorySize, smem);

    hist_kernel<<<NSAMP / 256, 256>>>(pos_r, neg_r);
    scan_kernel<<<1, 1024>>>();
    scatter_kernel<<<NSAMP / 256, 256>>>(pos_h, pos_t, pos_r, neg_h, neg_t, neg_r);
    score_loss_kernel<<<GRID_CTAS, STHREADS, smem>>>(ent, rel, out);
}